// round 14
// baseline (speedup 1.0000x reference)
#include <cuda_runtime.h>
#include <cuda_bf16.h>

// EntNet forward, dead-code-eliminated (see prior rounds).
// R5 structure (best: 65.6us) + L2 PREFETCH OVERLAP:
//  - during k_colpart/k_softmax/k_u (serial small-kernel window, DRAM idle),
//    extra blocks stream slices of H into L2 (40 MB total)
//  - during k_v (H now largely L2-hit -> DRAM idle), extra blocks stream 24 MB of R
// Prefetch blocks accumulate loads into a deterministic sink (not removable).
// Compute blocks are byte-identical to the 65.6us kernel.

#define D 4096
#define M 1024
#define L 8192
#define SPLITS 32
#define ROWS_PER 128        // D / SPLITS

// prefetch geometry: 1 chunk = 8192 float4 = 128 KB
#define PF_CHUNK_F4 8192
#define PF_H1 128           // colpart: 16 MB  (chunks 0..127)
#define PF_H2 64            // softmax:  8 MB  (chunks 128..191)
#define PF_H3 128           // k_u:     16 MB  (chunks 192..319)  -> 40 MB of H
#define PF_R  192           // k_v:     24 MB of R (chunks 0..191)

__device__ float g_sq[D];
__device__ float g_u[D];
__device__ float g_v[D];
__device__ float g_c[M];
__device__ float g_pdot[SPLITS * M];
__device__ float g_pss[SPLITS * M];
__device__ float g_sink[512];   // prefetch sums (deterministic, unused)

__device__ __forceinline__ float warp_reduce_sum(float v) {
#pragma unroll
    for (int o = 16; o > 0; o >>= 1) v += __shfl_down_sync(0xFFFFFFFFu, v, o);
    return v;
}
__device__ __forceinline__ float dot4(float4 a, float4 b) {
    return a.x * b.x + a.y * b.y + a.z * b.z + a.w * b.w;
}
__device__ __forceinline__ float4 ldcs4(const float4* p) { return __ldcs(p); }

// Stream one 128KB chunk into L2 (default policy). 256 threads, 32 f4 each.
__device__ __forceinline__ void prefetch_chunk_256(const float4* base4,
                                                   int chunk, int sink_idx) {
    const float4* p = base4 + (size_t)chunk * PF_CHUNK_F4;
    float acc = 0.f;
#pragma unroll 8
    for (int i = 0; i < 32; i++) {
        float4 v = __ldg(&p[threadIdx.x + i * 256]);
        acc += (v.x + v.y) + (v.z + v.w);
    }
    acc = warp_reduce_sum(acc);
    if (threadIdx.x == 0) g_sink[sink_idx & 511] = acc;
}

// ---------------------------------------------------------------------------
// K1: s_q[d] = dot(F_q[d,:], query) — warp-per-row, 64 f4/lane (R5 verbatim)
// ---------------------------------------------------------------------------
__global__ __launch_bounds__(256) void k_sq(const float* __restrict__ F,
                                            const float* __restrict__ q) {
    int warp = threadIdx.x >> 5, lane = threadIdx.x & 31;
    int row = blockIdx.x * 8 + warp;
    const float4* Fr = reinterpret_cast<const float4*>(F + (size_t)row * L);
    const float4* q4 = reinterpret_cast<const float4*>(q);
    float a0 = 0.f, a1 = 0.f, a2 = 0.f, a3 = 0.f;
#pragma unroll 4
    for (int k = 0; k < 64; k += 4) {
        int i0 = lane + (k + 0) * 32;
        int i1 = lane + (k + 1) * 32;
        int i2 = lane + (k + 2) * 32;
        int i3 = lane + (k + 3) * 32;
        float4 f0 = ldcs4(&Fr[i0]);
        float4 f1 = ldcs4(&Fr[i1]);
        float4 f2 = ldcs4(&Fr[i2]);
        float4 f3 = ldcs4(&Fr[i3]);
        a0 += dot4(f0, __ldg(&q4[i0]));
        a1 += dot4(f1, __ldg(&q4[i1]));
        a2 += dot4(f2, __ldg(&q4[i2]));
        a3 += dot4(f3, __ldg(&q4[i3]));
    }
    float acc = warp_reduce_sum((a0 + a1) + (a2 + a3));
    if (lane == 0) g_sq[row] = acc;
}

// ---------------------------------------------------------------------------
// K2: column partials (blocks 0..127) + H prefetch (blocks 128..255)
// ---------------------------------------------------------------------------
__global__ __launch_bounds__(256) void k_colpart(const float* __restrict__ mn,
                                                 const float* __restrict__ Hm) {
    int b = blockIdx.x;
    if (b >= 4 * SPLITS) {
        int p = b - 4 * SPLITS;            // 0..PF_H1-1
        prefetch_chunk_256(reinterpret_cast<const float4*>(Hm), p, p);
        return;
    }
    int j = (b & 3) * 256 + threadIdx.x;
    int s = b >> 2;
    __shared__ float shq[ROWS_PER];
    if (threadIdx.x < ROWS_PER) shq[threadIdx.x] = g_sq[s * ROWS_PER + threadIdx.x];
    __syncthreads();

    const float* base = mn + (size_t)s * ROWS_PER * M + j;
    float d0 = 0.f, d1 = 0.f, s0 = 0.f, s1 = 0.f;
#pragma unroll 8
    for (int d = 0; d < ROWS_PER; d += 2) {
        float v0 = base[(size_t)d * M];
        float v1 = base[(size_t)(d + 1) * M];
        d0 += v0 * shq[d];
        d1 += v1 * shq[d + 1];
        s0 += v0 * v0;
        s1 += v1 * v1;
    }
    g_pdot[s * M + j] = d0 + d1;
    g_pss [s * M + j] = s0 + s1;
}

// ---------------------------------------------------------------------------
// K3: softmax (block 0) + H prefetch (blocks 1..PF_H2). 256 threads/block:
// softmax handles 4 j per thread.
// ---------------------------------------------------------------------------
__global__ __launch_bounds__(256) void k_softmax(const float* __restrict__ Hm) {
    if (blockIdx.x > 0) {
        int p = blockIdx.x - 1;            // 0..PF_H2-1
        prefetch_chunk_256(reinterpret_cast<const float4*>(Hm), PF_H1 + p, 128 + p);
        return;
    }
    int lane = threadIdx.x & 31, wid = threadIdx.x >> 5;
    float tval[4], nrm[4];
#pragma unroll
    for (int k = 0; k < 4; k++) {
        int j = threadIdx.x + k * 256;
        float dot = 0.f, ss = 0.f;
#pragma unroll
        for (int s = 0; s < SPLITS; ++s) {
            dot += g_pdot[s * M + j];
            ss  += g_pss [s * M + j];
        }
        float n = fmaxf(sqrtf(ss), 1e-12f);
        nrm[k] = n;
        tval[k] = dot / n;
    }
    __shared__ float red[8];
    __shared__ float bcast;

    float m = fmaxf(fmaxf(tval[0], tval[1]), fmaxf(tval[2], tval[3]));
#pragma unroll
    for (int o = 16; o > 0; o >>= 1) m = fmaxf(m, __shfl_down_sync(0xFFFFFFFFu, m, o));
    if (lane == 0) red[wid] = m;
    __syncthreads();
    if (wid == 0) {
        float x = (lane < 8) ? red[lane] : -1e30f;
#pragma unroll
        for (int o = 4; o > 0; o >>= 1) x = fmaxf(x, __shfl_down_sync(0xFFFFFFFFu, x, o));
        if (lane == 0) bcast = x;
    }
    __syncthreads();
    float tmax = bcast;

    float e[4];
    float loc = 0.f;
#pragma unroll
    for (int k = 0; k < 4; k++) { e[k] = expf(tval[k] - tmax); loc += e[k]; }
    float su = warp_reduce_sum(loc);
    __syncthreads();
    if (lane == 0) red[wid] = su;
    __syncthreads();
    if (wid == 0) {
        float x = (lane < 8) ? red[lane] : 0.f;
#pragma unroll
        for (int o = 4; o > 0; o >>= 1) x += __shfl_down_sync(0xFFFFFFFFu, x, o);
        if (lane == 0) bcast = x;
    }
    __syncthreads();
    float esum = bcast;
#pragma unroll
    for (int k = 0; k < 4; k++) {
        int j = threadIdx.x + k * 256;
        g_c[j] = e[k] / (esum * nrm[k]);
    }
}

// ---------------------------------------------------------------------------
// K4: u = mn @ c (blocks 0..511, R5 verbatim) + H prefetch (512..639)
// ---------------------------------------------------------------------------
__global__ __launch_bounds__(256) void k_u(const float* __restrict__ mn,
                                           const float* __restrict__ Hm) {
    if (blockIdx.x >= 512) {
        int p = blockIdx.x - 512;          // 0..PF_H3-1
        prefetch_chunk_256(reinterpret_cast<const float4*>(Hm),
                           PF_H1 + PF_H2 + p, 192 + p);
        return;
    }
    int warp = threadIdx.x >> 5, lane = threadIdx.x & 31;
    int row = blockIdx.x * 8 + warp;
    const float4* r  = reinterpret_cast<const float4*>(mn + (size_t)row * M);
    const float4* c4 = reinterpret_cast<const float4*>(g_c);
    float a0 = 0.f, a1 = 0.f, a2 = 0.f, a3 = 0.f;
    int i0 = lane,       i1 = lane + 32,  i2 = lane + 64,  i3 = lane + 96;
    int i4 = lane + 128, i5 = lane + 160, i6 = lane + 192, i7 = lane + 224;
    float4 m0 = r[i0];
    float4 m1 = r[i1];
    float4 m2 = r[i2];
    float4 m3 = r[i3];
    float4 m4 = r[i4];
    float4 m5 = r[i5];
    float4 m6 = r[i6];
    float4 m7 = r[i7];
    a0 += dot4(m0, __ldg(&c4[i0]));
    a1 += dot4(m1, __ldg(&c4[i1]));
    a2 += dot4(m2, __ldg(&c4[i2]));
    a3 += dot4(m3, __ldg(&c4[i3]));
    a0 += dot4(m4, __ldg(&c4[i4]));
    a1 += dot4(m5, __ldg(&c4[i5]));
    a2 += dot4(m6, __ldg(&c4[i6]));
    a3 += dot4(m7, __ldg(&c4[i7]));
    float acc = warp_reduce_sum((a0 + a1) + (a2 + a3));
    if (lane == 0) g_u[row] = acc;
}

// ---------------------------------------------------------------------------
// K5: v = prelu(s_q + H@u) (blocks 0..511) + R prefetch (512..703)
// H reads via ldcs: hit prefetched L2 lines, then mark evict-first for R.
// ---------------------------------------------------------------------------
__global__ __launch_bounds__(256) void k_v(const float* __restrict__ H,
                                           const float* __restrict__ Rm,
                                           const float* __restrict__ a_out) {
    if (blockIdx.x >= 512) {
        int p = blockIdx.x - 512;          // 0..PF_R-1
        prefetch_chunk_256(reinterpret_cast<const float4*>(Rm), p, 320 + p);
        return;
    }
    int warp = threadIdx.x >> 5, lane = threadIdx.x & 31;
    int row = blockIdx.x * 8 + warp;
    const float4* Hr = reinterpret_cast<const float4*>(H + (size_t)row * D);
    const float4* u4 = reinterpret_cast<const float4*>(g_u);
    float a0 = 0.f, a1 = 0.f, a2 = 0.f, a3 = 0.f;
#pragma unroll 4
    for (int k = 0; k < 32; k += 4) {
        int i0 = lane + (k + 0) * 32;
        int i1 = lane + (k + 1) * 32;
        int i2 = lane + (k + 2) * 32;
        int i3 = lane + (k + 3) * 32;
        float4 f0 = ldcs4(&Hr[i0]);
        float4 f1 = ldcs4(&Hr[i1]);
        float4 f2 = ldcs4(&Hr[i2]);
        float4 f3 = ldcs4(&Hr[i3]);
        a0 += dot4(f0, __ldg(&u4[i0]));
        a1 += dot4(f1, __ldg(&u4[i1]));
        a2 += dot4(f2, __ldg(&u4[i2]));
        a3 += dot4(f3, __ldg(&u4[i3]));
    }
    float acc = warp_reduce_sum((a0 + a1) + (a2 + a3));
    if (lane == 0) {
        float x = g_sq[row] + acc;
        float a = __ldg(a_out);
        g_v[row] = (x >= 0.f) ? x : a * x;
    }
}

// ---------------------------------------------------------------------------
// K6: y = R @ v — (R5 verbatim; R partially L2-hot) -> d_out
// ---------------------------------------------------------------------------
__global__ __launch_bounds__(256) void k_y(const float* __restrict__ R,
                                           float* __restrict__ out) {
    int warp = threadIdx.x >> 5, lane = threadIdx.x & 31;
    int row = blockIdx.x * 8 + warp;
    const float4* Rr = reinterpret_cast<const float4*>(R + (size_t)row * D);
    const float4* v4 = reinterpret_cast<const float4*>(g_v);
    float a0 = 0.f, a1 = 0.f, a2 = 0.f, a3 = 0.f;
#pragma unroll 4
    for (int k = 0; k < 32; k += 4) {
        int i0 = lane + (k + 0) * 32;
        int i1 = lane + (k + 1) * 32;
        int i2 = lane + (k + 2) * 32;
        int i3 = lane + (k + 3) * 32;
        float4 f0 = ldcs4(&Rr[i0]);
        float4 f1 = ldcs4(&Rr[i1]);
        float4 f2 = ldcs4(&Rr[i2]);
        float4 f3 = ldcs4(&Rr[i3]);
        a0 += dot4(f0, __ldg(&v4[i0]));
        a1 += dot4(f1, __ldg(&v4[i1]));
        a2 += dot4(f2, __ldg(&v4[i2]));
        a3 += dot4(f3, __ldg(&v4[i3]));
    }
    float acc = warp_reduce_sum((a0 + a1) + (a2 + a3));
    if (lane == 0) out[row] = acc;
}

extern "C" void kernel_launch(void* const* d_in, const int* in_sizes, int n_in,
                              void* d_out, int out_size) {
    // metadata order: input, query, F_i, F_q, keys, memory_nodes, U, V, W, R, H, a_mem, a_out
    const float* query = (const float*)d_in[1];
    const float* F_q   = (const float*)d_in[3];
    const float* mn    = (const float*)d_in[5];
    const float* Rm    = (const float*)d_in[9];
    const float* Hm    = (const float*)d_in[10];
    const float* a_out = (const float*)d_in[12];
    float* out = (float*)d_out;

    k_sq<<<D / 8, 256>>>(F_q, query);
    k_colpart<<<4 * SPLITS + PF_H1, 256>>>(mn, Hm);
    k_softmax<<<1 + PF_H2, 256>>>(Hm);
    k_u<<<512 + PF_H3, 256>>>(mn, Hm);
    k_v<<<512 + PF_R, 256>>>(Hm, Rm, a_out);
    k_y<<<D / 8, 256>>>(Rm, out);
}